// round 1
// baseline (speedup 1.0000x reference)
#include <cuda_runtime.h>
#include <math.h>

// Problem constants (fixed by the dataset)
#define B  8
#define C  64
#define Hc 256
#define Wc 256
#define CR 128
#define HR 128   // readout H
#define WR 128   // readout W

// Scratch (no allocations allowed)
__device__ float g_scores[B * CR];
__device__ int   g_idx[B * C];

// ---------------------------------------------------------------------------
// Kernel 1: per-(b,cr) score = mean of bilinear-2x-upsampled plane.
// Mean of upsampled = separable weighted sum over the 128x128 input.
// ---------------------------------------------------------------------------
__global__ void scores_kernel(const float* __restrict__ readout) {
    __shared__ float wA[HR];
    __shared__ float red[256];
    const int tid = threadIdx.x;

    if (tid < HR) wA[tid] = 0.0f;
    __syncthreads();

    // aggregate axis weights: each output position j contributes (1-w) to i0, w to i0+1
    {
        const float cst = (float)(127.0 / 255.0);
        float pos = (float)tid * cst;        // tid in [0,255]
        int i0 = (int)pos;
        if (i0 > HR - 2) i0 = HR - 2;
        float w = pos - (float)i0;
        atomicAdd(&wA[i0], 1.0f - w);
        atomicAdd(&wA[i0 + 1], w);
    }
    __syncthreads();

    const int plane = blockIdx.x;  // b*CR + cr
    const float4* src = (const float4*)(readout + (size_t)plane * (HR * WR));

    float acc = 0.0f;
    #pragma unroll 4
    for (int i = tid; i < (HR * WR) / 4; i += 256) {
        float4 v = src[i];
        int base = i << 2;
        int row = base >> 7;       // WR = 128
        int col = base & 127;
        float wr = wA[row];
        acc += wr * (wA[col] * v.x + wA[col + 1] * v.y +
                     wA[col + 2] * v.z + wA[col + 3] * v.w);
    }

    red[tid] = acc;
    __syncthreads();
    for (int s = 128; s > 0; s >>= 1) {
        if (tid < s) red[tid] += red[tid + s];
        __syncthreads();
    }
    if (tid == 0) g_scores[plane] = red[0] * (1.0f / (float)(Hc * Wc));
}

// ---------------------------------------------------------------------------
// Kernel 2: per-batch descending bitonic sort of 128 scores (tie: lower idx
// first, matching jax.lax.top_k). Writes the top C=64 indices.
// ---------------------------------------------------------------------------
__global__ void topk_kernel() {
    __shared__ float sv[CR];
    __shared__ int   si[CR];
    const int tid = threadIdx.x;  // 0..127
    const int b = blockIdx.x;

    sv[tid] = g_scores[b * CR + tid];
    si[tid] = tid;
    __syncthreads();

    for (int k = 2; k <= CR; k <<= 1) {
        for (int j = k >> 1; j > 0; j >>= 1) {
            int ixj = tid ^ j;
            if (ixj > tid) {
                float va = sv[tid], vb = sv[ixj];
                int   ia = si[tid], ib = si[ixj];
                // "tid element should precede ixj element" in DESC order
                bool first = (va > vb) || (va == vb && ia < ib);
                bool ascSeg = ((tid & k) == 0);
                bool doSwap = ascSeg ? (!first) : first;
                if (doSwap) {
                    sv[tid] = vb; sv[ixj] = va;
                    si[tid] = ib; si[ixj] = ia;
                }
            }
            __syncthreads();
        }
    }

    if (tid < C) g_idx[b * C + tid] = si[tid];
}

// ---------------------------------------------------------------------------
// Kernel 3: fused on-the-fly bilinear upsample of selected channel + gated
// blend. Each thread produces 4 contiguous output pixels (float4 I/O).
// ---------------------------------------------------------------------------
__global__ void __launch_bounds__(256) fuse_kernel(
    const float* __restrict__ x,
    const float* __restrict__ readout,
    const float* __restrict__ weight,
    const float* __restrict__ bias,
    float* __restrict__ out)
{
    const int plane = blockIdx.z;            // b*C + c
    const int b = plane >> 6;
    const int c = plane & (C - 1);
    const int ch = g_idx[plane];

    const float* __restrict__ rsrc =
        readout + ((size_t)b * CR + ch) * (HR * WR);

    const int y  = blockIdx.y * blockDim.y + threadIdx.y;
    const int x0 = (blockIdx.x * blockDim.x + threadIdx.x) << 2;

    const float cst = (float)(127.0 / 255.0);
    float posy = (float)y * cst;
    int iy0 = (int)posy;
    if (iy0 > HR - 2) iy0 = HR - 2;
    const float wy = posy - (float)iy0;
    const float wy0 = 1.0f - wy;

    const float* __restrict__ row0 = rsrc + iy0 * WR;
    const float* __restrict__ row1 = row0 + WR;

    const float w0 = __ldg(weight + 2 * c);
    const float w1 = __ldg(weight + 2 * c + 1);
    const float bs = __ldg(bias + c);

    const size_t o = ((size_t)plane * Hc + y) * Wc + x0;
    float4 xv = *(const float4*)(x + o);

    float rv[4];
    #pragma unroll
    for (int k = 0; k < 4; k++) {
        float posx = (float)(x0 + k) * cst;
        int ix0 = (int)posx;
        if (ix0 > WR - 2) ix0 = WR - 2;
        float wx = posx - (float)ix0;
        // match reference: interpolate along H first, then W
        float a  = __ldg(row0 + ix0)     * wy0 + __ldg(row1 + ix0)     * wy;
        float bb = __ldg(row0 + ix0 + 1) * wy0 + __ldg(row1 + ix0 + 1) * wy;
        rv[k] = a * (1.0f - wx) + bb * wx;
    }

    float xs[4] = {xv.x, xv.y, xv.z, xv.w};
    float os[4];
    #pragma unroll
    for (int k = 0; k < 4; k++) {
        float t = xs[k] * w0 + rv[k] * w1 + bs;
        float gate = 1.0f / (1.0f + __expf(-t));
        os[k] = xs[k] + gate * (rv[k] - xs[k]);
    }

    *(float4*)(out + o) = make_float4(os[0], os[1], os[2], os[3]);
}

// ---------------------------------------------------------------------------
extern "C" void kernel_launch(void* const* d_in, const int* in_sizes, int n_in,
                              void* d_out, int out_size)
{
    const float* x       = (const float*)d_in[0];
    const float* readout = (const float*)d_in[1];
    const float* weight  = (const float*)d_in[2];
    const float* bias    = (const float*)d_in[3];
    float* out = (float*)d_out;

    scores_kernel<<<B * CR, 256>>>(readout);
    topk_kernel<<<B, CR>>>();

    dim3 blk(64, 4, 1);                 // 64 threads * 4 px = 256 px in x, 4 rows
    dim3 grd(1, Hc / 4, B * C);         // (1, 64, 512)
    fuse_kernel<<<grd, blk>>>(x, readout, weight, bias, out);
}

// round 2
// speedup vs baseline: 1.0610x; 1.0610x over previous
#include <cuda_runtime.h>
#include <math.h>

// Problem constants (fixed by the dataset)
#define B  8
#define C  64
#define Hc 256
#define Wc 256
#define CR 128
#define HR 128   // readout H
#define WR 128   // readout W

// Scratch (no allocations allowed)
__device__ float g_scores[B * CR];
__device__ int   g_idx[B * C];

// ---------------------------------------------------------------------------
// Kernel 1: per-(b,cr) score = mean of bilinear-2x-upsampled plane.
// Mean of upsampled = separable weighted sum over the 128x128 input.
// High-MLP version: 16 front-batched float4 loads, 4 independent accumulators.
// ---------------------------------------------------------------------------
__global__ void __launch_bounds__(256) scores_kernel(const float* __restrict__ readout) {
    __shared__ float wA[HR];
    __shared__ float red[8];
    const int tid = threadIdx.x;

    if (tid < HR) wA[tid] = 0.0f;
    __syncthreads();

    {
        const float cst = (float)(127.0 / 255.0);
        float pos = (float)tid * cst;        // tid in [0,255]
        int i0 = (int)pos;
        if (i0 > HR - 2) i0 = HR - 2;
        float w = pos - (float)i0;
        atomicAdd(&wA[i0], 1.0f - w);
        atomicAdd(&wA[i0 + 1], w);
    }
    __syncthreads();

    const int plane = blockIdx.x;  // b*CR + cr
    const float4* __restrict__ src =
        (const float4*)(readout + (size_t)plane * (HR * WR));

    float acc0 = 0.f, acc1 = 0.f, acc2 = 0.f, acc3 = 0.f;

    // 4096 float4 per plane / 256 threads = 16 per thread; two batches of 8
    #pragma unroll
    for (int half = 0; half < 2; half++) {
        float4 v[8];
        #pragma unroll
        for (int j = 0; j < 8; j++)
            v[j] = src[tid + (half * 8 + j) * 256];

        #pragma unroll
        for (int j = 0; j < 8; j++) {
            int base = (tid + (half * 8 + j) * 256) << 2;
            int row = base >> 7;       // WR = 128
            int col = base & 127;
            float wr = wA[row];
            float s = wA[col] * v[j].x + wA[col + 1] * v[j].y +
                      wA[col + 2] * v[j].z + wA[col + 3] * v[j].w;
            if (j == 0 || j == 4) acc0 += wr * s;
            else if (j == 1 || j == 5) acc1 += wr * s;
            else if (j == 2 || j == 6) acc2 += wr * s;
            else acc3 += wr * s;
        }
    }

    float acc = (acc0 + acc1) + (acc2 + acc3);
    // warp reduce
    #pragma unroll
    for (int s = 16; s > 0; s >>= 1)
        acc += __shfl_down_sync(0xffffffffu, acc, s);
    if ((tid & 31) == 0) red[tid >> 5] = acc;
    __syncthreads();
    if (tid == 0) {
        float t = 0.f;
        #pragma unroll
        for (int w2 = 0; w2 < 8; w2++) t += red[w2];
        g_scores[plane] = t * (1.0f / (float)(Hc * Wc));
    }
}

// ---------------------------------------------------------------------------
// Kernel 2: per-batch descending bitonic sort of 128 scores (tie: lower idx
// first, matching jax.lax.top_k). Writes the top C=64 indices.
// ---------------------------------------------------------------------------
__global__ void topk_kernel() {
    __shared__ float sv[CR];
    __shared__ int   si[CR];
    const int tid = threadIdx.x;  // 0..127
    const int b = blockIdx.x;

    sv[tid] = g_scores[b * CR + tid];
    si[tid] = tid;
    __syncthreads();

    for (int k = 2; k <= CR; k <<= 1) {
        for (int j = k >> 1; j > 0; j >>= 1) {
            int ixj = tid ^ j;
            if (ixj > tid) {
                float va = sv[tid], vb = sv[ixj];
                int   ia = si[tid], ib = si[ixj];
                bool first = (va > vb) || (va == vb && ia < ib);
                bool ascSeg = ((tid & k) == 0);
                bool doSwap = ascSeg ? (!first) : first;
                if (doSwap) {
                    sv[tid] = vb; sv[ixj] = va;
                    si[tid] = ib; si[ixj] = ia;
                }
            }
            __syncthreads();
        }
    }

    if (tid < C) g_idx[b * C + tid] = si[tid];
}

// ---------------------------------------------------------------------------
// Kernel 3: fused on-the-fly bilinear upsample + gated blend.
// Block = 8 output rows x 256 cols of one plane. The <=5 readout rows the
// block needs are staged into shared memory (coalesced float4), so each
// thread's global traffic is exactly 2x float4 streamed loads + 2x float4
// streamed stores; all bilinear taps are LDS.
// ---------------------------------------------------------------------------
__global__ void __launch_bounds__(256) fuse_kernel(
    const float* __restrict__ x,
    const float* __restrict__ readout,
    const float* __restrict__ weight,
    const float* __restrict__ bias,
    float* __restrict__ out)
{
    __shared__ float srow[6 * WR];

    const int plane = blockIdx.z;            // b*C + c
    const int b = plane >> 6;
    const int c = plane & (C - 1);
    const int ch = g_idx[plane];

    const float* __restrict__ rsrc =
        readout + ((size_t)b * CR + ch) * (HR * WR);

    const int y0 = blockIdx.y << 3;          // 8 rows per block
    const float cst = (float)(127.0 / 255.0);

    int iy_lo = (int)((float)y0 * cst);       if (iy_lo > HR - 2) iy_lo = HR - 2;
    int iy_hi = (int)((float)(y0 + 7) * cst); if (iy_hi > HR - 2) iy_hi = HR - 2;
    iy_hi += 1;
    const int nrows = iy_hi - iy_lo + 1;      // <= 5

    const int tid = threadIdx.x;
    if (tid < nrows * 32) {
        int row = tid >> 5;
        int col = (tid & 31) << 2;
        float4 v = *(const float4*)(rsrc + (iy_lo + row) * WR + col);
        *(float4*)(srow + row * WR + col) = v;
    }
    __syncthreads();

    const int tx = tid & 63;
    const int ty = tid >> 6;                  // 0..3
    const int x0 = tx << 2;

    const float w0 = __ldg(weight + 2 * c);
    const float w1 = __ldg(weight + 2 * c + 1);
    const float bs = __ldg(bias + c);

    int   ixA[4];
    float wxA[4];
    #pragma unroll
    for (int k = 0; k < 4; k++) {
        float posx = (float)(x0 + k) * cst;
        int ix0 = (int)posx;
        if (ix0 > WR - 2) ix0 = WR - 2;
        ixA[k] = ix0;
        wxA[k] = posx - (float)ix0;
    }

    #pragma unroll
    for (int r = 0; r < 2; r++) {
        const int y = y0 + ty + (r << 2);
        float posy = (float)y * cst;
        int iy0 = (int)posy;
        if (iy0 > HR - 2) iy0 = HR - 2;
        const float wy = posy - (float)iy0;
        const float wy0 = 1.0f - wy;

        const float* __restrict__ s0 = srow + (iy0 - iy_lo) * WR;
        const float* __restrict__ s1 = s0 + WR;

        const size_t o = ((size_t)plane * Hc + y) * Wc + x0;
        float4 xv = __ldcs((const float4*)(x + o));
        float xs[4] = {xv.x, xv.y, xv.z, xv.w};
        float os[4];

        #pragma unroll
        for (int k = 0; k < 4; k++) {
            int ix0 = ixA[k];
            // match reference: interpolate H first, then W
            float a  = s0[ix0]     * wy0 + s1[ix0]     * wy;
            float bb = s0[ix0 + 1] * wy0 + s1[ix0 + 1] * wy;
            float rv = a * (1.0f - wxA[k]) + bb * wxA[k];
            float t = xs[k] * w0 + rv * w1 + bs;
            float gate = 1.0f / (1.0f + __expf(-t));
            os[k] = xs[k] + gate * (rv - xs[k]);
        }

        __stcs((float4*)(out + o), make_float4(os[0], os[1], os[2], os[3]));
    }
}

// ---------------------------------------------------------------------------
extern "C" void kernel_launch(void* const* d_in, const int* in_sizes, int n_in,
                              void* d_out, int out_size)
{
    const float* x       = (const float*)d_in[0];
    const float* readout = (const float*)d_in[1];
    const float* weight  = (const float*)d_in[2];
    const float* bias    = (const float*)d_in[3];
    float* out = (float*)d_out;

    scores_kernel<<<B * CR, 256>>>(readout);
    topk_kernel<<<B, CR>>>();

    dim3 blk(256, 1, 1);
    dim3 grd(1, Hc / 8, B * C);   // (1, 32, 512)
    fuse_kernel<<<grd, blk>>>(x, readout, weight, bias, out);
}